// round 16
// baseline (speedup 1.0000x reference)
#include <cuda_runtime.h>

// Problem constants
#define TSEQ 1024
#define NB   32      // batch
#define ID   512     // input dim
#define HD   512     // hidden dim
#define GD   2048    // 4*H gate rows
#define NBLK_DIR 64  // persistent blocks per direction (8 hidden units each)
#define REC_THREADS 256

typedef unsigned long long ull;

union F4U { float4 f; ulonglong2 u; };

// Scratch (device globals: no runtime allocation allowed)
__device__ float g_xw[(size_t)TSEQ * GD * NB];   // [t][g][b], 256MB
__device__ float g_hbuf[2][2][HD * NB];          // [dir][ping][u*32 + b]
__device__ unsigned g_barcnt[2];   // flat barrier arrival counters (monotonic)

// ---------------------------------------------------------------------------
// packed fp32x2 ops (Blackwell)
// ---------------------------------------------------------------------------
__device__ __forceinline__ void ffma2(ull& d, ull a, ull b) {
    asm("fma.rn.f32x2 %0, %1, %2, %0;" : "+l"(d) : "l"(a), "l"(b));
}
__device__ __forceinline__ ull addf2(ull a, ull b) {
    ull r;
    asm("add.rn.f32x2 %0, %1, %2;" : "=l"(r) : "l"(a), "l"(b));
    return r;
}
__device__ __forceinline__ ull dup2(float x) {
    ull r;
    asm("mov.b64 %0, {%1, %1};" : "=l"(r) : "f"(x));
    return r;
}
__device__ __forceinline__ float pairsum(ull v) {
    float2 f = *reinterpret_cast<float2*>(&v);
    return f.x + f.y;
}

__device__ __forceinline__ unsigned ld_acquire(const unsigned* p) {
    unsigned v;
    asm volatile("ld.acquire.gpu.u32 %0, [%1];" : "=r"(v) : "l"(p) : "memory");
    return v;
}

__device__ __forceinline__ float sigf(float x) {
    return __fdividef(1.f, 1.f + __expf(-x));
}
__device__ __forceinline__ float tanhfast(float x) {
    return __fdividef(2.f, 1.f + __expf(-2.f * x)) - 1.f;
}

// ---------------------------------------------------------------------------
// Flat per-direction barrier, counter-only (R13-proven)
// ---------------------------------------------------------------------------
__device__ __forceinline__ void bar_arrive_red(int dir) {
    asm volatile("red.release.gpu.global.add.u32 [%0], %1;"
                 :: "l"(&g_barcnt[dir]), "r"(1u) : "memory");
}
__device__ __forceinline__ void bar_wait_cnt(int dir, unsigned target) {
    while ((int)(ld_acquire(&g_barcnt[dir]) - target) < 0) { }
}

// ---------------------------------------------------------------------------
// xw v3: register-tiled GEMM with PRE-DUPLICATED W pairs in smem.
// Block = (t, 64-gate group), 256 threads. Warp w -> gates 8w..8w+7,
// all 32 batches. lane = (ks = lane>>3 [4-way k], bq = lane&7 [2 bp]).
// Inner iter: 4 LDS.128 (dup'd W) + 1 LDS.128 (x pairs) + 16 FFMA2, no MOVs.
// ws2 stride 66 ull: ks-group reads land on disjoint bank quartets (1 wf).
// Single end-of-kernel 2-round shfl_xor k-fold (static selects), direct STG.
// ---------------------------------------------------------------------------
__global__ void __launch_bounds__(256, 2) xw_gemm(
    const float* __restrict__ x,
    const float* __restrict__ Wih,
    const float* __restrict__ bih,
    const float* __restrict__ bhh,
    float4* __restrict__ out4)
{
    __shared__ ull   ws2[32 * 66];  // [kk][g] dup'd pairs, stride 66 (16.9KB)
    __shared__ float xs[32 * 36];   // [kk][b], stride 36 (4.6KB)

    int t   = blockIdx.x >> 5;
    int g0  = (blockIdx.x & 31) << 6;
    int tid = threadIdx.x;
    int w   = tid >> 5;
    int lane = tid & 31;
    int ks  = lane >> 3;
    int bq  = lane & 7;

    // zero this block's 2KB slice of d_out (atomicAdd target for the recurrence)
    if (tid < 128)
        out4[(size_t)blockIdx.x * 128 + tid] = make_float4(0.f, 0.f, 0.f, 0.f);

    // final gate subset of this lane after the fold: gb = 4*(ks&1) + 2*(ks>>1)
    int gb = ((ks & 1) << 2) | (ks & 2);
    float bias0 = bih[g0 + 8 * w + gb]     + bhh[g0 + 8 * w + gb];
    float bias1 = bih[g0 + 8 * w + gb + 1] + bhh[g0 + 8 * w + gb + 1];

    ull acc[8][2];
#pragma unroll
    for (int i = 0; i < 8; i++) { acc[i][0] = 0ull; acc[i][1] = 0ull; }

    const float* xt = x + (size_t)t * NB * ID;

    // load-index precomputes
    int gl = tid >> 2, mq = tid & 3;      // W loader: gate gl, 8-k group mq
    int bl = tid >> 3, mm = tid & 7;      // x loader: batch bl, 4-k group mm

    for (int kc = 0; kc < ID; kc += 32) {
        __syncthreads();   // previous GEMV reads done before overwrite
        // W chunk -> ws2[kk][g] as dup'd (w,w) pairs
        {
            const float4* src = (const float4*)(Wih + (size_t)(g0 + gl) * ID + kc + 8 * mq);
            float4 a = src[0], b = src[1];
            ull* wp = ws2 + gl;
            wp[(8 * mq + 0) * 66] = dup2(a.x);
            wp[(8 * mq + 1) * 66] = dup2(a.y);
            wp[(8 * mq + 2) * 66] = dup2(a.z);
            wp[(8 * mq + 3) * 66] = dup2(a.w);
            wp[(8 * mq + 4) * 66] = dup2(b.x);
            wp[(8 * mq + 5) * 66] = dup2(b.y);
            wp[(8 * mq + 6) * 66] = dup2(b.z);
            wp[(8 * mq + 7) * 66] = dup2(b.w);
        }
        // x chunk -> xs[kk][b] (k-major)
        {
            float4 v = *(const float4*)(xt + bl * ID + kc + 4 * mm);
            float* xp = xs + bl;
            xp[(4 * mm + 0) * 36] = v.x;
            xp[(4 * mm + 1) * 36] = v.y;
            xp[(4 * mm + 2) * 36] = v.z;
            xp[(4 * mm + 3) * 36] = v.w;
        }
        __syncthreads();

        // GEMV: 8 iters, k = 4*it + ks per lane; all operands pre-packed
#pragma unroll
        for (int it = 0; it < 8; it++) {
            int kk = (it << 2) | ks;
            const ull* wrow = ws2 + kk * 66 + 8 * w;
            ulonglong2 w01 = *(const ulonglong2*)(wrow);
            ulonglong2 w23 = *(const ulonglong2*)(wrow + 2);
            ulonglong2 w45 = *(const ulonglong2*)(wrow + 4);
            ulonglong2 w67 = *(const ulonglong2*)(wrow + 6);
            ulonglong2 xv = *(const ulonglong2*)(xs + kk * 36 + 4 * bq);
            ffma2(acc[0][0], w01.x, xv.x); ffma2(acc[0][1], w01.x, xv.y);
            ffma2(acc[1][0], w01.y, xv.x); ffma2(acc[1][1], w01.y, xv.y);
            ffma2(acc[2][0], w23.x, xv.x); ffma2(acc[2][1], w23.x, xv.y);
            ffma2(acc[3][0], w23.y, xv.x); ffma2(acc[3][1], w23.y, xv.y);
            ffma2(acc[4][0], w45.x, xv.x); ffma2(acc[4][1], w45.x, xv.y);
            ffma2(acc[5][0], w45.y, xv.x); ffma2(acc[5][1], w45.y, xv.y);
            ffma2(acc[6][0], w67.x, xv.x); ffma2(acc[6][1], w67.x, xv.y);
            ffma2(acc[7][0], w67.y, xv.x); ffma2(acc[7][1], w67.y, xv.y);
        }
    }

    // 2-round k-fold across the 4 ks groups (STATIC register indices only).
    bool kA = (lane & 8) != 0;    // ks bit 0
    bool kB = (lane & 16) != 0;   // ks bit 1
    ull kept[4][2];
#pragma unroll
    for (int j = 0; j < 4; j++)
#pragma unroll
        for (int p = 0; p < 2; p++) {
            ull snd = kA ? acc[j][p] : acc[j + 4][p];
            ull rcv = __shfl_xor_sync(0xFFFFFFFFu, snd, 8);
            kept[j][p] = addf2(kA ? acc[j + 4][p] : acc[j][p], rcv);
        }
    ull fin[2][2];
#pragma unroll
    for (int j = 0; j < 2; j++)
#pragma unroll
        for (int p = 0; p < 2; p++) {
            ull snd = kB ? kept[j][p] : kept[j + 2][p];
            ull rcv = __shfl_xor_sync(0xFFFFFFFFu, snd, 16);
            fin[j][p] = addf2(kB ? kept[j + 2][p] : kept[j][p], rcv);
        }

    // add bias (broadcast over the batch pair) and store
    {
        ull b0 = dup2(bias0), b1 = dup2(bias1);
        float* outp = g_xw + ((size_t)t * GD + g0 + 8 * w + gb) * NB + 4 * bq;
        *(ull*)(outp)           = addf2(fin[0][0], b0);
        *(ull*)(outp + 2)       = addf2(fin[0][1], b0);
        *(ull*)(outp + NB)      = addf2(fin[1][0], b1);
        *(ull*)(outp + NB + 2)  = addf2(fin[1][1], b1);
    }
}

// ---------------------------------------------------------------------------
// Persistent bidirectional zoneout-LSTM recurrence (R13 structure).
// R16 delta: NO smem h staging — GEMV reads h directly from g_hbuf via
// __ldcg LDG.128 (L2-resident; latency hidden by unroll-4 MLP inside the
// fma-bound GEMV). Removes the copy's serial latency from the step path.
// ---------------------------------------------------------------------------
__global__ __launch_bounds__(REC_THREADS, 1) void lstm_rec(
    const float* __restrict__ Whh, float* __restrict__ out)
{
    extern __shared__ float smem[];
    float* Wt   = smem;             // 64KB: Wt[k*32 + row]
    float* gbuf = smem + 16384;     // 34KB: gbuf[w*1088 + row*34 + b]

    int bid  = blockIdx.x;
    int dir  = bid >> 6;
    int j0   = (bid & 63) << 3;
    int tid  = threadIdx.x;
    int w    = tid >> 5;
    int lane = tid & 31;
    int ks0  = lane >> 4;
    int rg   = (lane >> 2) & 3;
    int bg   = lane & 3;
    int u_l  = w;               // cell phase: unit-local 0..7
    int gu   = j0 + u_l;

    // Stage W_hh once: Wt[k*32 + row], row -> global W row (row>>3)*512 + j0 + (row&7)
#pragma unroll 4
    for (int i = 0; i < 64; i++) {
        int idx = tid + (i << 8);
        int row = idx >> 9;
        int k   = idx & 511;
        int gr  = ((row >> 3) << 9) + j0 + (row & 7);
        Wt[k * 32 + row] = Whh[(size_t)gr * HD + k];
    }

    // init h(step 0) = 0 (own units); c and h_old live in registers
    float c_reg = 0.f;
    float h_reg = 0.f;
    g_hbuf[dir][0][gu * 32 + lane] = 0.f;

    // barrier base for this launch (monotonic counter, replay-safe)
    unsigned base = ld_acquire(&g_barcnt[dir]) & ~(unsigned)(NBLK_DIR - 1);

    __syncthreads();
    if (tid == 0) bar_arrive_red(dir);     // publish h0

    const float4* W4 = (const float4*)Wt;
    const int kbeg = (w << 6) + (ks0 << 5);

    for (int s = 0; s < TSEQ; s++) {
        int t = dir ? (TSEQ - 1 - s) : s;
        const float* xw_t = g_xw + (size_t)t * GD * NB;

        // prefetch xw BEFORE the wait: DRAM latency hidden under the spin
        float xg0 = xw_t[(0 * HD + gu) * NB + lane];
        float xg1 = xw_t[(1 * HD + gu) * NB + lane];
        float xg2 = xw_t[(2 * HD + gu) * NB + lane];
        float xg3 = xw_t[(3 * HD + gu) * NB + lane];

        // wait: all 64 blocks of this direction have published h_s
        if (tid == 0) bar_wait_cnt(dir, base + (unsigned)NBLK_DIR * (s + 1));
        __syncthreads();

        const float4* Ghb4 = (const float4*)g_hbuf[dir][s & 1];

        // GEMV: 8 rows x 4 batch-pairs per lane over 32 k; h direct from L2
        ull acc[8][4];
#pragma unroll
        for (int i = 0; i < 8; i++)
#pragma unroll
            for (int j = 0; j < 4; j++) acc[i][j] = 0ull;

#pragma unroll 4
        for (int kk = 0; kk < 32; kk++) {
            int k = kbeg + kk;
            float4 wA = W4[(k << 3) + (rg << 1)];       // rows 8rg..8rg+3
            float4 wB = W4[(k << 3) + (rg << 1) + 1];   // rows 8rg+4..8rg+7
            F4U tA, tB;
            tA.f = __ldcg(&Ghb4[(k << 3) + (bg << 1)]);     // batches 8bg..+3
            tB.f = __ldcg(&Ghb4[(k << 3) + (bg << 1) + 1]); // batches 8bg+4..+7
            float wf[8] = {wA.x, wA.y, wA.z, wA.w, wB.x, wB.y, wB.z, wB.w};
#pragma unroll
            for (int i = 0; i < 8; i++) {
                ull wd = dup2(wf[i]);
                ffma2(acc[i][0], wd, tA.u.x);
                ffma2(acc[i][1], wd, tA.u.y);
                ffma2(acc[i][2], wd, tB.u.x);
                ffma2(acc[i][3], wd, tB.u.y);
            }
        }

        // fold k-halves + store: STATIC indices only (R7 lesson)
        {
            float* gp0 = gbuf + w * 1088 + (bg << 3) + (ks0 << 2);
#pragma unroll
            for (int i = 0; i < 8; i++) {
                ull s0 = ks0 ? acc[i][0] : acc[i][2];
                ull s1 = ks0 ? acc[i][1] : acc[i][3];
                ull r0 = __shfl_xor_sync(0xFFFFFFFFu, s0, 16);
                ull r1 = __shfl_xor_sync(0xFFFFFFFFu, s1, 16);
                ull k0 = ks0 ? acc[i][2] : acc[i][0];
                ull k1 = ks0 ? acc[i][3] : acc[i][1];
                ull v0 = addf2(k0, r0);
                ull v1 = addf2(k1, r1);
                float* gp = gp0 + ((rg << 3) + i) * 34;
                *(ull*)gp = v0;
                *(ull*)(gp + 2) = v1;
            }
        }
        __syncthreads();

        // cell update: thread = (unit u_l = w, batch lane); 8 partial sets per gate
        {
            int b = lane;
            float iv = xg0, fv = xg1, gv = xg2, ov = xg3;
#pragma unroll
            for (int sw = 0; sw < 8; sw++) {
                const float* gp = gbuf + sw * 1088 + b;
                iv += gp[(0 * 8 + u_l) * 34];
                fv += gp[(1 * 8 + u_l) * 34];
                gv += gp[(2 * 8 + u_l) * 34];
                ov += gp[(3 * 8 + u_l) * 34];
            }
            iv = sigf(iv);
            fv = sigf(fv);
            gv = tanhfast(gv);
            ov = sigf(ov);
            float c_new = fv * c_reg + iv * gv;
            float h_new = ov * tanhfast(c_new);
            c_reg = 0.9f * c_new + 0.1f * c_reg;
            float h_bl = 0.9f * h_new + 0.1f * h_reg;
            h_reg = h_bl;
            g_hbuf[dir][(s + 1) & 1][gu * 32 + lane] = h_bl;
            // exactly two commutative fp32 adds per output element -> deterministic
            atomicAdd(&out[(size_t)t * (NB * HD) + lane * HD + gu], h_bl);
        }

        // publish h_{s+1}
        __syncthreads();
        if (tid == 0) bar_arrive_red(dir);
    }
}

// ---------------------------------------------------------------------------
extern "C" void kernel_launch(void* const* d_in, const int* in_sizes, int n_in,
                              void* d_out, int out_size) {
    const float* x   = (const float*)d_in[0];
    const float* Wih = (const float*)d_in[1];
    const float* Whh = (const float*)d_in[2];
    const float* bih = (const float*)d_in[3];
    const float* bhh = (const float*)d_in[4];
    float* out = (float*)d_out;

    const int rec_smem = (16384 + 8 * 1088) * (int)sizeof(float); // 100352 B
    cudaFuncSetAttribute(lstm_rec, cudaFuncAttributeMaxDynamicSharedMemorySize, rec_smem);

    xw_gemm<<<TSEQ * 32, 256>>>(x, Wih, bih, bhh, (float4*)out);
    lstm_rec<<<2 * NBLK_DIR, REC_THREADS, rec_smem>>>(Whh, out);
}